// round 7
// baseline (speedup 1.0000x reference)
#include <cuda_runtime.h>
#include <cuda_fp16.h>
#include <cstdint>

// SplineGCN round 7: ILP for the latency-bound passes.
//   K1 histprep : col/row histograms (4 edges/thread) + weight permute
//   K2 scan1    : per-chunk exclusive scan of BOTH histograms (self-cleans g_hist)
//   K3 scan3    : adds inline partial prefix; writes startc/curc/curr
//   K4 scatter  : 4 edges/thread; packed col-sorted records + row-sorted msg slots
//   K5 fused    : 48-node Z tile (fp16, smem) via mma.sync, edge gather from LDS, msg store
//   K6 final    : segmented mean (unroll-4, 2 accumulator banks) + bias (self-cleans g_degi)

#define MAXN 50176            // 196 * 256
#define MAXE 1605632
#define KO 2048               // 64 kernels * 32 out
#define NPB 48                // source nodes per fused block
#define ZS 2056               // smem Z row stride in halfs (4112B)
#define NCHUNK 196            // MAXN / 256
#define NPART 392             // 2 * NCHUNK

__device__ uint32_t g_Bperm[16 * KO];
__device__ int      g_hist[MAXN];       // col histogram (zeroed by scan1 after read)
__device__ int      g_degi[MAXN];       // row histogram (zeroed by final after read)
__device__ int      g_startc[MAXN];     // col segment starts
__device__ int      g_curc[MAXN];       // col scatter cursor
__device__ int      g_curr[MAXN];       // row slot cursor (holds segment END after scatter)
__device__ int      g_part[NPART];
__device__ uint4    g_rec[MAXE];        // {col, q0|q1, q2|base<<16, msg_slot}
__device__ __half   g_msg[(size_t)MAXE * 32];

static __device__ __forceinline__ uint32_t h2u(__half2 h) {
    return *reinterpret_cast<uint32_t*>(&h);
}

// ---------------- K1: histograms (4 edges/thread) + weight permute ----------------
__global__ void histprep_kernel(const int* __restrict__ ei,
                                const float* __restrict__ w, int E, int HB) {
    if ((int)blockIdx.x < HB) {
        int b0 = blockIdx.x * 1024 + threadIdx.x;
        int r[4], c[4];
        bool v[4];
#pragma unroll
        for (int j = 0; j < 4; j++) {
            int e = b0 + j * 256;
            v[j] = e < E;
            if (v[j]) { r[j] = ei[e]; c[j] = ei[E + e]; }
        }
#pragma unroll
        for (int j = 0; j < 4; j++) {
            if (v[j]) {
                atomicAdd(&g_hist[c[j]], 1);
                atomicAdd(&g_degi[r[j]], 1);
            }
        }
    } else {
        int i = (blockIdx.x - HB) * 256 + threadIdx.x;   // < 32768
        int kk = i >> 11, cc = i & 2047;
        int k = cc >> 5, o = cc & 31;
        float w0 = w[k * 1024 + (2 * kk) * 32 + o];
        float w1 = w[k * 1024 + (2 * kk + 1) * 32 + o];
        g_Bperm[i] = h2u(__floats2half2_rn(w0, w1));
    }
}

// ---------------- K2: per-chunk exclusive scan of both histograms ----------------
__global__ void scan1_kernel() {
    __shared__ int sh[256];
    int b = blockIdx.x, t = threadIdx.x;
    bool isB = b >= NCHUNK;
    int i = (isB ? b - NCHUNK : b) * 256 + t;
    int v = isB ? g_degi[i] : g_hist[i];
    sh[t] = v; __syncthreads();
#pragma unroll
    for (int o = 1; o < 256; o <<= 1) {
        int u = (t >= o) ? sh[t - o] : 0;
        __syncthreads();
        sh[t] += u;
        __syncthreads();
    }
    int ex = sh[t] - v;
    if (isB) {
        g_curr[i] = ex;
    } else {
        g_startc[i] = ex;
        g_hist[i] = 0;          // self-clean for next replay
    }
    if (t == 255) g_part[b] = sh[255];
}

// ---------------- K3: add partial prefix (computed inline) ----------------
__global__ void scan3_kernel() {
    __shared__ int red[256];
    int b = blockIdx.x, t = threadIdx.x;
    bool isB = b >= NCHUNK;
    int lo = isB ? NCHUNK : 0;

    int acc = 0;
    if (t >= lo && t < b) acc += g_part[t];
    int t2 = t + 256;
    if (t2 >= lo && t2 < b && t2 < NPART) acc += g_part[t2];
    red[t] = acc; __syncthreads();
#pragma unroll
    for (int o = 128; o > 0; o >>= 1) {
        if (t < o) red[t] += red[t + o];
        __syncthreads();
    }
    int pp = red[0];

    int i = (isB ? b - NCHUNK : b) * 256 + t;
    if (!isB) {
        int v = g_startc[i] + pp;
        g_startc[i] = v;
        g_curc[i] = v;
    } else {
        g_curr[i] += pp;
    }
}

// ---------------- K4: scatter, 4 edges/thread ----------------
__global__ void __launch_bounds__(256) scatter_kernel(const float* __restrict__ pseudo,
                                                      const int* __restrict__ ei, int E) {
    int b0 = blockIdx.x * 1024 + threadIdx.x;
    int row[4], col[4];
    uint32_t py[4], pz[4];
    bool v[4];
#pragma unroll
    for (int j = 0; j < 4; j++) {
        int e = b0 + j * 256;
        v[j] = e < E;
        if (!v[j]) continue;
        row[j] = ei[e];
        col[j] = ei[E + e];
        float v0 = pseudo[e * 3 + 0] * 3.0f;
        float v1 = pseudo[e * 3 + 1] * 3.0f;
        float v2 = pseudo[e * 3 + 2] * 3.0f;
        int b0i = (int)v0; b0i = b0i > 2 ? 2 : b0i;
        int b1i = (int)v1; b1i = b1i > 2 ? 2 : b1i;
        int b2i = (int)v2; b2i = b2i > 2 ? 2 : b2i;
        float f0 = v0 - (float)b0i, f1 = v1 - (float)b1i, f2 = v2 - (float)b2i;
        int base = b0i + (b1i << 2) + (b2i << 4);
        int q0 = min((int)(f0 * 65536.0f), 65535);
        int q1 = min((int)(f1 * 65536.0f), 65535);
        int q2 = min((int)(f2 * 65536.0f), 65535);
        py[j] = (uint32_t)q0 | ((uint32_t)q1 << 16);
        pz[j] = (uint32_t)q2 | ((uint32_t)base << 16);
    }
    int posc[4], posr[4];
#pragma unroll
    for (int j = 0; j < 4; j++)
        if (v[j]) posc[j] = atomicAdd(&g_curc[col[j]], 1);
#pragma unroll
    for (int j = 0; j < 4; j++)
        if (v[j]) posr[j] = atomicAdd(&g_curr[row[j]], 1);
#pragma unroll
    for (int j = 0; j < 4; j++)
        if (v[j])
            g_rec[posc[j]] = make_uint4((uint32_t)col[j], py[j], pz[j], (uint32_t)posr[j]);
}

static __device__ __forceinline__ uint32_t lda(const float* __restrict__ f, int r, int c, int n) {
    if (r >= n) return 0u;
    float2 v = *reinterpret_cast<const float2*>(f + (size_t)r * 32 + c);
    return h2u(__floats2half2_rn(v.x, v.y));
}

// ---------------- K5: fused Z tile + edge gather + msg store (1024 threads) ----------------
__global__ void __launch_bounds__(1024) fused_kernel(const float* __restrict__ feat, int n, int E) {
    extern __shared__ uint32_t sZ32[];          // NPB rows * ZS halfs
    const int tid = threadIdx.x;
    const int warp = tid >> 5, lane = tid & 31;
    const int g = lane >> 2, t4 = lane & 3;
    const int nb0 = blockIdx.x * NPB;

    // ---- phase 1: Z[nb0..nb0+48) = feat @ W, fp16 into smem; warp owns 64 cols ----
    uint32_t a[3][2][4];
#pragma unroll
    for (int rg = 0; rg < 3; rg++) {
#pragma unroll
        for (int ks = 0; ks < 2; ks++) {
            int c0 = ks * 16 + t4 * 2;
            int r0 = nb0 + rg * 16 + g;
            a[rg][ks][0] = lda(feat, r0, c0, n);
            a[rg][ks][1] = lda(feat, r0 + 8, c0, n);
            a[rg][ks][2] = lda(feat, r0, c0 + 8, n);
            a[rg][ks][3] = lda(feat, r0 + 8, c0 + 8, n);
        }
    }

    const int colbase = warp * 64;
#pragma unroll 4
    for (int nb = 0; nb < 8; nb++) {
        int c = colbase + nb * 8 + g;
        uint32_t b[2][2];
#pragma unroll
        for (int ks = 0; ks < 2; ks++) {
            b[ks][0] = g_Bperm[((ks * 8 + t4) << 11) + c];
            b[ks][1] = g_Bperm[((ks * 8 + t4 + 4) << 11) + c];
        }
#pragma unroll
        for (int rg = 0; rg < 3; rg++) {
            float c0 = 0.f, c1 = 0.f, c2 = 0.f, c3 = 0.f;
#pragma unroll
            for (int ks = 0; ks < 2; ks++) {
                asm volatile(
                    "mma.sync.aligned.m16n8k16.row.col.f32.f16.f16.f32 "
                    "{%0,%1,%2,%3}, {%4,%5,%6,%7}, {%8,%9}, {%0,%1,%2,%3};"
                    : "+f"(c0), "+f"(c1), "+f"(c2), "+f"(c3)
                    : "r"(a[rg][ks][0]), "r"(a[rg][ks][1]), "r"(a[rg][ks][2]), "r"(a[rg][ks][3]),
                      "r"(b[ks][0]), "r"(b[ks][1]));
            }
            int row0 = rg * 16 + g;
            int ch2 = (colbase >> 1) + nb * 4 + t4;
            sZ32[row0 * (ZS / 2) + ch2]       = h2u(__floats2half2_rn(c0, c1));
            sZ32[(row0 + 8) * (ZS / 2) + ch2] = h2u(__floats2half2_rn(c2, c3));
        }
    }
    __syncthreads();

    // ---- phase 2: edges of these 48 nodes gather from smem, store fp16 msg ----
    const __half* sZ = reinterpret_cast<const __half*>(sZ32);
    int estart = g_startc[nb0];
    int eend   = g_startc[nb0 + NPB];   // nb0+NPB <= 50016 < MAXN
    int l4 = tid & 3;

    for (int i = estart + (tid >> 2); i < eend; i += 256) {
        uint4 r = __ldg(&g_rec[i]);
        int local = (int)r.x - nb0;
        const float iq = 1.0f / 65536.0f;
        float f0 = (float)(r.y & 0xFFFF) * iq;
        float f1 = (float)(r.y >> 16) * iq;
        float f2 = (float)(r.z & 0xFFFF) * iq;
        int base = r.z >> 16;

        // precompute the 8 trilinear weights once
        float e0 = 1.0f - f0, e1 = 1.0f - f1, e2 = 1.0f - f2;
        float w01 = e0 * e1, w11 = f0 * e1, w02 = e0 * f1, w12 = f0 * f1;
        float wc[8];
        wc[0] = w01 * e2; wc[1] = w11 * e2; wc[2] = w02 * e2; wc[3] = w12 * e2;
        wc[4] = w01 * f2; wc[5] = w11 * f2; wc[6] = w02 * f2; wc[7] = w12 * f2;

        const __half* zp = sZ + local * ZS + l4 * 8;

        float a0 = 0.f, a1 = 0.f, a2 = 0.f, a3 = 0.f, a4 = 0.f, a5 = 0.f, a6 = 0.f, a7 = 0.f;
#pragma unroll
        for (int s = 0; s < 8; s++) {
            float w = wc[s];
            int k = base + (s & 1) + ((s & 2) << 1) + ((s & 4) << 2);
            uint4 u = *reinterpret_cast<const uint4*>(zp + (k << 5));
            float2 p0 = __half22float2(*reinterpret_cast<__half2*>(&u.x));
            float2 p1 = __half22float2(*reinterpret_cast<__half2*>(&u.y));
            float2 p2 = __half22float2(*reinterpret_cast<__half2*>(&u.z));
            float2 p3 = __half22float2(*reinterpret_cast<__half2*>(&u.w));
            a0 = fmaf(w, p0.x, a0); a1 = fmaf(w, p0.y, a1);
            a2 = fmaf(w, p1.x, a2); a3 = fmaf(w, p1.y, a3);
            a4 = fmaf(w, p2.x, a4); a5 = fmaf(w, p2.y, a5);
            a6 = fmaf(w, p3.x, a6); a7 = fmaf(w, p3.y, a7);
        }
        uint4 m;
        m.x = h2u(__floats2half2_rn(a0, a1));
        m.y = h2u(__floats2half2_rn(a2, a3));
        m.z = h2u(__floats2half2_rn(a4, a5));
        m.w = h2u(__floats2half2_rn(a6, a7));
        *reinterpret_cast<uint4*>(g_msg + (size_t)r.w * 32 + l4 * 8) = m;
    }
}

// ---------------- K6: segmented mean + bias (self-cleans g_degi) ----------------
__global__ void __launch_bounds__(512) final_kernel(float* __restrict__ out,
                                                    const float* __restrict__ bias, int n) {
    int t = blockIdx.x * blockDim.x + threadIdx.x;
    int node = t >> 2;
    if (node >= n) return;
    int l4 = t & 3;

    int deg = g_degi[node];
    int start = g_curr[node] - deg;     // cursor holds segment end after scatter

    float a0 = 0.f, a1 = 0.f, a2 = 0.f, a3 = 0.f, a4 = 0.f, a5 = 0.f, a6 = 0.f, a7 = 0.f;
    float b0 = 0.f, b1 = 0.f, b2 = 0.f, b3 = 0.f, b4 = 0.f, b5 = 0.f, b6 = 0.f, b7 = 0.f;
    const __half* mp = g_msg + (size_t)start * 32 + l4 * 8;
    int j = 0;
    for (; j + 1 < deg; j += 2) {
        uint4 u = __ldg(reinterpret_cast<const uint4*>(mp + (size_t)j * 32));
        uint4 w = __ldg(reinterpret_cast<const uint4*>(mp + (size_t)(j + 1) * 32));
        float2 p0 = __half22float2(*reinterpret_cast<__half2*>(&u.x));
        float2 p1 = __half22float2(*reinterpret_cast<__half2*>(&u.y));
        float2 p2 = __half22float2(*reinterpret_cast<__half2*>(&u.z));
        float2 p3 = __half22float2(*reinterpret_cast<__half2*>(&u.w));
        a0 += p0.x; a1 += p0.y; a2 += p1.x; a3 += p1.y;
        a4 += p2.x; a5 += p2.y; a6 += p3.x; a7 += p3.y;
        float2 q0 = __half22float2(*reinterpret_cast<__half2*>(&w.x));
        float2 q1 = __half22float2(*reinterpret_cast<__half2*>(&w.y));
        float2 q2 = __half22float2(*reinterpret_cast<__half2*>(&w.z));
        float2 q3 = __half22float2(*reinterpret_cast<__half2*>(&w.w));
        b0 += q0.x; b1 += q0.y; b2 += q1.x; b3 += q1.y;
        b4 += q2.x; b5 += q2.y; b6 += q3.x; b7 += q3.y;
    }
    if (j < deg) {
        uint4 u = __ldg(reinterpret_cast<const uint4*>(mp + (size_t)j * 32));
        float2 p0 = __half22float2(*reinterpret_cast<__half2*>(&u.x));
        float2 p1 = __half22float2(*reinterpret_cast<__half2*>(&u.y));
        float2 p2 = __half22float2(*reinterpret_cast<__half2*>(&u.z));
        float2 p3 = __half22float2(*reinterpret_cast<__half2*>(&u.w));
        a0 += p0.x; a1 += p0.y; a2 += p1.x; a3 += p1.y;
        a4 += p2.x; a5 += p2.y; a6 += p3.x; a7 += p3.y;
    }
    a0 += b0; a1 += b1; a2 += b2; a3 += b3;
    a4 += b4; a5 += b5; a6 += b6; a7 += b7;

    float inv = 1.0f / fmaxf((float)deg, 1.0f);
    const float* bp = bias + l4 * 8;
    float* dst = out + (size_t)node * 32 + l4 * 8;
    float4 o0 = make_float4(a0 * inv + bp[0], a1 * inv + bp[1],
                            a2 * inv + bp[2], a3 * inv + bp[3]);
    float4 o1 = make_float4(a4 * inv + bp[4], a5 * inv + bp[5],
                            a6 * inv + bp[6], a7 * inv + bp[7]);
    *reinterpret_cast<float4*>(dst) = o0;
    *reinterpret_cast<float4*>(dst + 4) = o1;

    if (l4 == 0) g_degi[node] = 0;      // self-clean for next replay
}

extern "C" void kernel_launch(void* const* d_in, const int* in_sizes, int n_in,
                              void* d_out, int out_size) {
    const float* feat   = (const float*)d_in[0];
    const float* pseudo = (const float*)d_in[1];
    const float* weight = (const float*)d_in[2];
    const float* bias   = (const float*)d_in[3];
    const int*   ei     = (const int*)d_in[4];
    int n = in_sizes[0] / 32;
    int E = in_sizes[4] / 2;
    float* out = (float*)d_out;

    const int smem_bytes = NPB * ZS * 2;                // 197376 B
    static int configured = 0;
    if (!configured) {
        cudaFuncSetAttribute(fused_kernel, cudaFuncAttributeMaxDynamicSharedMemorySize, smem_bytes);
        configured = 1;
    }

    int HB = (E + 1023) / 1024;   // 4 edges/thread blocks
    histprep_kernel<<<HB + 128, 256>>>(ei, weight, E, HB);
    scan1_kernel<<<NPART, 256>>>();
    scan3_kernel<<<NPART, 256>>>();
    scatter_kernel<<<(E + 1023) / 1024, 256>>>(pseudo, ei, E);
    fused_kernel<<<(n + NPB - 1) / NPB, 1024, smem_bytes>>>(feat, n, E);
    final_kernel<<<(n * 4 + 511) / 512, 512>>>(out, bias, n);
}

// round 8
// speedup vs baseline: 1.2235x; 1.2235x over previous
#include <cuda_runtime.h>
#include <cuda_fp16.h>
#include <cstdint>

// SplineGCN round 8 (base = R6 shapes, which measured 198.8):
//   - row-sort/msg buffer DELETED: fused scatters fp32 messages via red.global.add.v4
//   - scatter has ONE returning atomic per edge (col cursor only)
//   - final is elementwise divide+bias
//   K1 histprep : col/row histograms + weight permute + zero out
//   K2 scan1    : per-chunk exclusive scan of col histogram (self-cleans g_hist)
//   K3 scan3    : adds inline partial prefix -> startc/curc
//   K4 scatter  : packed col-sorted records (1 atomic/edge)
//   K5 fused    : 48-node Z tile (fp16, smem) via mma.sync, edge gather from LDS,
//                 red.global.add.v4.f32 into out
//   K6 final    : out = out/deg + bias (self-cleans g_degi)

#define MAXN 50176            // 196 * 256
#define MAXE 1605632
#define KO 2048               // 64 kernels * 32 out
#define NPB 48                // source nodes per fused block
#define ZS 2056               // smem Z row stride in halfs (4112B)
#define NCHUNK 196            // MAXN / 256

__device__ uint32_t g_Bperm[16 * KO];
__device__ int      g_hist[MAXN];       // col histogram (zeroed by scan1 after read)
__device__ int      g_degi[MAXN];       // row degree (zeroed by final after read)
__device__ int      g_startc[MAXN];     // col segment starts
__device__ int      g_curc[MAXN];       // col scatter cursor
__device__ int      g_part[NCHUNK];
__device__ uint4    g_rec[MAXE];        // {row, q0|q1, q2|base<<16, col}

static __device__ __forceinline__ uint32_t h2u(__half2 h) {
    return *reinterpret_cast<uint32_t*>(&h);
}

// ---------------- K1: histograms + weight permute + zero out ----------------
__global__ void histprep_kernel(const int* __restrict__ ei,
                                const float* __restrict__ w,
                                float* __restrict__ out,
                                int E, int n, int HB) {
    int b = blockIdx.x;
    if (b < HB) {
        int e = b * 256 + threadIdx.x;
        if (e < E) {
            atomicAdd(&g_hist[ei[E + e]], 1);   // source bins
            atomicAdd(&g_degi[ei[e]], 1);       // target degree
        }
    } else if (b < HB + 128) {
        int i = (b - HB) * 256 + threadIdx.x;   // < 32768
        int kk = i >> 11, cc = i & 2047;
        int k = cc >> 5, o = cc & 31;
        float w0 = w[k * 1024 + (2 * kk) * 32 + o];
        float w1 = w[k * 1024 + (2 * kk + 1) * 32 + o];
        g_Bperm[i] = h2u(__floats2half2_rn(w0, w1));
    } else {
        int i = (b - HB - 128) * 256 + threadIdx.x;
        if (i < n * 32) out[i] = 0.0f;
    }
}

// ---------------- K2: per-chunk exclusive scan of col histogram ----------------
__global__ void scan1_kernel() {
    __shared__ int sh[256];
    int t = threadIdx.x, i = blockIdx.x * 256 + t;
    int v = g_hist[i];
    sh[t] = v; __syncthreads();
#pragma unroll
    for (int o = 1; o < 256; o <<= 1) {
        int u = (t >= o) ? sh[t - o] : 0;
        __syncthreads();
        sh[t] += u;
        __syncthreads();
    }
    g_startc[i] = sh[t] - v;
    g_hist[i] = 0;              // self-clean for next replay
    if (t == 255) g_part[blockIdx.x] = sh[255];
}

// ---------------- K3: add partial prefix (computed inline) ----------------
__global__ void scan3_kernel() {
    __shared__ int red[256];
    int b = blockIdx.x, t = threadIdx.x;
    int acc = (t < b) ? g_part[t] : 0;
    red[t] = acc; __syncthreads();
#pragma unroll
    for (int o = 128; o > 0; o >>= 1) {
        if (t < o) red[t] += red[t + o];
        __syncthreads();
    }
    int pp = red[0];
    int i = b * 256 + t;
    int v = g_startc[i] + pp;
    g_startc[i] = v;
    g_curc[i] = v;
}

// ---------------- K4: scatter into col-sorted, packed records ----------------
__global__ void scatter_kernel(const float* __restrict__ pseudo,
                               const int* __restrict__ ei, int E) {
    int e = blockIdx.x * blockDim.x + threadIdx.x;
    if (e >= E) return;
    int row = ei[e];
    int col = ei[E + e];

    float v0 = pseudo[e * 3 + 0] * 3.0f;
    float v1 = pseudo[e * 3 + 1] * 3.0f;
    float v2 = pseudo[e * 3 + 2] * 3.0f;
    int b0 = (int)v0; b0 = b0 > 2 ? 2 : b0;
    int b1 = (int)v1; b1 = b1 > 2 ? 2 : b1;
    int b2 = (int)v2; b2 = b2 > 2 ? 2 : b2;
    float f0 = v0 - (float)b0, f1 = v1 - (float)b1, f2 = v2 - (float)b2;
    int base = b0 + (b1 << 2) + (b2 << 4);

    int q0 = min((int)(f0 * 65536.0f), 65535);
    int q1 = min((int)(f1 * 65536.0f), 65535);
    int q2 = min((int)(f2 * 65536.0f), 65535);

    int posc = atomicAdd(&g_curc[col], 1);
    g_rec[posc] = make_uint4((uint32_t)row,
                             (uint32_t)q0 | ((uint32_t)q1 << 16),
                             (uint32_t)q2 | ((uint32_t)base << 16),
                             (uint32_t)col);
}

static __device__ __forceinline__ uint32_t lda(const float* __restrict__ f, int r, int c, int n) {
    if (r >= n) return 0u;
    float2 v = *reinterpret_cast<const float2*>(f + (size_t)r * 32 + c);
    return h2u(__floats2half2_rn(v.x, v.y));
}

// ---------------- K5: fused Z tile + edge gather + red.global scatter ----------------
__global__ void __launch_bounds__(1024) fused_kernel(const float* __restrict__ feat,
                                                     float* __restrict__ out, int n, int E) {
    extern __shared__ uint32_t sZ32[];          // NPB rows * ZS halfs
    const int tid = threadIdx.x;
    const int warp = tid >> 5, lane = tid & 31;
    const int g = lane >> 2, t4 = lane & 3;
    const int nb0 = blockIdx.x * NPB;

    // ---- phase 1: Z[nb0..nb0+48) = feat @ W, fp16 into smem; warp owns 64 cols ----
    uint32_t a[3][2][4];
#pragma unroll
    for (int rg = 0; rg < 3; rg++) {
#pragma unroll
        for (int ks = 0; ks < 2; ks++) {
            int c0 = ks * 16 + t4 * 2;
            int r0 = nb0 + rg * 16 + g;
            a[rg][ks][0] = lda(feat, r0, c0, n);
            a[rg][ks][1] = lda(feat, r0 + 8, c0, n);
            a[rg][ks][2] = lda(feat, r0, c0 + 8, n);
            a[rg][ks][3] = lda(feat, r0 + 8, c0 + 8, n);
        }
    }

    const int colbase = warp * 64;
#pragma unroll 4
    for (int nb = 0; nb < 8; nb++) {
        int c = colbase + nb * 8 + g;
        uint32_t b[2][2];
#pragma unroll
        for (int ks = 0; ks < 2; ks++) {
            b[ks][0] = g_Bperm[((ks * 8 + t4) << 11) + c];
            b[ks][1] = g_Bperm[((ks * 8 + t4 + 4) << 11) + c];
        }
#pragma unroll
        for (int rg = 0; rg < 3; rg++) {
            float c0 = 0.f, c1 = 0.f, c2 = 0.f, c3 = 0.f;
#pragma unroll
            for (int ks = 0; ks < 2; ks++) {
                asm volatile(
                    "mma.sync.aligned.m16n8k16.row.col.f32.f16.f16.f32 "
                    "{%0,%1,%2,%3}, {%4,%5,%6,%7}, {%8,%9}, {%0,%1,%2,%3};"
                    : "+f"(c0), "+f"(c1), "+f"(c2), "+f"(c3)
                    : "r"(a[rg][ks][0]), "r"(a[rg][ks][1]), "r"(a[rg][ks][2]), "r"(a[rg][ks][3]),
                      "r"(b[ks][0]), "r"(b[ks][1]));
            }
            int row0 = rg * 16 + g;
            int ch2 = (colbase >> 1) + nb * 4 + t4;
            sZ32[row0 * (ZS / 2) + ch2]       = h2u(__floats2half2_rn(c0, c1));
            sZ32[(row0 + 8) * (ZS / 2) + ch2] = h2u(__floats2half2_rn(c2, c3));
        }
    }
    __syncthreads();

    // ---- phase 2: edges of these 48 nodes gather from smem, red into out ----
    const __half* sZ = reinterpret_cast<const __half*>(sZ32);
    int estart = g_startc[nb0];
    int eend   = g_startc[nb0 + NPB];   // nb0+NPB <= 50160 < MAXN
    int l4 = tid & 3;

    for (int i = estart + (tid >> 2); i < eend; i += 256) {
        uint4 r = __ldg(&g_rec[i]);
        int row = (int)r.x;
        int local = (int)r.w - nb0;
        const float iq = 1.0f / 65536.0f;
        float f0 = (float)(r.y & 0xFFFF) * iq;
        float f1 = (float)(r.y >> 16) * iq;
        float f2 = (float)(r.z & 0xFFFF) * iq;
        int base = r.z >> 16;

        const __half* zp = sZ + local * ZS + l4 * 8;

        float a0 = 0.f, a1 = 0.f, a2 = 0.f, a3 = 0.f, a4 = 0.f, a5 = 0.f, a6 = 0.f, a7 = 0.f;
#pragma unroll
        for (int s = 0; s < 8; s++) {
            float w = ((s & 1) ? f0 : 1.0f - f0) *
                      ((s & 2) ? f1 : 1.0f - f1) *
                      ((s & 4) ? f2 : 1.0f - f2);
            int k = base + (s & 1) + ((s & 2) << 1) + ((s & 4) << 2);
            uint4 u = *reinterpret_cast<const uint4*>(zp + (k << 5));
            float2 p0 = __half22float2(*reinterpret_cast<__half2*>(&u.x));
            float2 p1 = __half22float2(*reinterpret_cast<__half2*>(&u.y));
            float2 p2 = __half22float2(*reinterpret_cast<__half2*>(&u.z));
            float2 p3 = __half22float2(*reinterpret_cast<__half2*>(&u.w));
            a0 = fmaf(w, p0.x, a0); a1 = fmaf(w, p0.y, a1);
            a2 = fmaf(w, p1.x, a2); a3 = fmaf(w, p1.y, a3);
            a4 = fmaf(w, p2.x, a4); a5 = fmaf(w, p2.y, a5);
            a6 = fmaf(w, p3.x, a6); a7 = fmaf(w, p3.y, a7);
        }
        float* dst = out + (size_t)row * 32 + l4 * 8;
        asm volatile("red.global.add.v4.f32 [%0], {%1,%2,%3,%4};"
                     :: "l"(dst), "f"(a0), "f"(a1), "f"(a2), "f"(a3) : "memory");
        asm volatile("red.global.add.v4.f32 [%0], {%1,%2,%3,%4};"
                     :: "l"(dst + 4), "f"(a4), "f"(a5), "f"(a6), "f"(a7) : "memory");
    }
}

// ---------------- K6: elementwise divide + bias (self-cleans g_degi) ----------------
__global__ void final_kernel(float* __restrict__ out, const float* __restrict__ bias, int n) {
    int i = blockIdx.x * blockDim.x + threadIdx.x;
    if (i >= n * 32) return;
    int node = i >> 5;
    float d = (float)g_degi[node];
    out[i] = out[i] / fmaxf(d, 1.0f) + bias[i & 31];
    if ((i & 31) == 0) g_degi[node] = 0;    // self-clean for next replay
}

extern "C" void kernel_launch(void* const* d_in, const int* in_sizes, int n_in,
                              void* d_out, int out_size) {
    const float* feat   = (const float*)d_in[0];
    const float* pseudo = (const float*)d_in[1];
    const float* weight = (const float*)d_in[2];
    const float* bias   = (const float*)d_in[3];
    const int*   ei     = (const int*)d_in[4];
    int n = in_sizes[0] / 32;
    int E = in_sizes[4] / 2;
    float* out = (float*)d_out;

    const int smem_bytes = NPB * ZS * 2;                // 197376 B
    static int configured = 0;
    if (!configured) {
        cudaFuncSetAttribute(fused_kernel, cudaFuncAttributeMaxDynamicSharedMemorySize, smem_bytes);
        configured = 1;
    }

    int HB = (E + 255) / 256;
    int ZB = (n * 32 + 255) / 256;
    histprep_kernel<<<HB + 128 + ZB, 256>>>(ei, weight, out, E, n, HB);
    scan1_kernel<<<NCHUNK, 256>>>();
    scan3_kernel<<<NCHUNK, 256>>>();
    scatter_kernel<<<(E + 255) / 256, 256>>>(pseudo, ei, E);
    fused_kernel<<<(n + NPB - 1) / NPB, 1024, smem_bytes>>>(feat, out, n, E);
    final_kernel<<<(n * 32 + 255) / 256, 256>>>(out, bias, n);
}